// round 4
// baseline (speedup 1.0000x reference)
#include <cuda_runtime.h>
#include <cstdint>
#include <math.h>

// BinaryTreeLatentVariable: N_LEAVES=1024, L=16, C=4.
// out[node,o] = parent[node,o] + mL + mR
//             + log( sum_{i,j} expT[o,i,j] * exp(L[i]-mL) * exp(R[j]-mR) )
// o=(lp,cp), i=(ll,cl), j=(lr,cr); 64 outputs/node, K=4096.

#define OC 64
#define KD 4096
#define NB 16     // nodes per pass

__device__ float g_ET[OC * KD];      // 1 MB: exp(trans) repacked [o][i][j]
__device__ float g_bufA[512 * OC];
__device__ float g_bufB[512 * OC];

// ---- packed f32x2 helpers (Blackwell FFMA2) --------------------------------
__device__ __forceinline__ unsigned long long pack2(float x, float y) {
    unsigned long long r;
    asm("mov.b64 %0, {%1, %2};" : "=l"(r) : "f"(x), "f"(y));
    return r;
}
__device__ __forceinline__ void unpack2(unsigned long long v, float& x, float& y) {
    asm("mov.b64 {%0, %1}, %2;" : "=f"(x), "=f"(y) : "l"(v));
}
__device__ __forceinline__ void ffma2(unsigned long long& d,
                                      unsigned long long a, unsigned long long b) {
    asm("fma.rn.f32x2 %0, %1, %2, %0;" : "+l"(d) : "l"(a), "l"(b));
}

// ---- Prologue: ET[o][i][j] = exp(trans[lp,ll,lr,cp,cl,cr]) -----------------
__global__ void expT_kernel(const float* __restrict__ trans) {
    int idx = blockIdx.x * 256 + threadIdx.x;   // 0 .. 262143
    int o = idx >> 12, i = (idx >> 6) & 63, j = idx & 63;
    int lp = o >> 2, cp = o & 3;
    int ll = i >> 2, cl = i & 3;
    int lr = j >> 2, cr = j & 3;
    int src = ((((lp * 16 + ll) * 16 + lr) * 4 + cp) * 4 + cl) * 4 + cr;
    g_ET[idx] = expf(trans[src]);
}

// ---------------------------------------------------------------------------
// One tree level, smem-resident ET.
// CTA: 256 threads / 8 warps. blockIdx.y = o-group (4 outputs).
// warp w: output g=w>>1 of the group, i-half = w&1 (32 i's each).
// ET slice (4 x 16KB = 64KB) cp.async'd to smem once; CTA then loops over
// its npc nodes in NB=16 chunks. Lane owns j = {2*lane, 2*lane+1}.
// Halves combine via smem; 64 threads do the log-epilogue.
// ---------------------------------------------------------------------------
__global__ __launch_bounds__(256, 2) void level_kernel(
    const float* __restrict__ leaves,
    const float* __restrict__ parent,
    float* __restrict__ final_out,
    int n, int npc, int child_sel, int out_sel)
{
    extern __shared__ float smem[];
    float* ET_s   = smem;                   // 4*4096 = 16384 floats
    float* eLs    = smem + 16384;           // [i][nb]   64*NB
    float* eRs    = eLs + 64 * NB;          // [nb][j]   NB*64
    float* base_s = eRs + NB * 64;          // NB
    float* part   = base_s + NB;            // [g][nb][half]  4*NB*2

    const float* child = (child_sel == 0) ? leaves
                        : (child_sel == 1) ? g_bufA : g_bufB;
    float* out = (out_sel == 1) ? g_bufA
               : (out_sel == 2) ? g_bufB : final_out;

    const int tid  = threadIdx.x;
    const int warp = tid >> 5;
    const int lane = tid & 31;
    const int og   = blockIdx.y;

    // ---- async ET slice load: 64 KB, 16B per cp.async ----
    {
        unsigned int dst;
        asm("{ .reg .u64 t; cvta.to.shared.u64 t, %1; cvt.u32.u64 %0, t; }"
            : "=r"(dst) : "l"(ET_s));
        const float4* src = reinterpret_cast<const float4*>(g_ET) + og * 4096;
        #pragma unroll 4
        for (int t = tid; t < 4096; t += 256) {
            asm volatile("cp.async.cg.shared.global [%0], [%1], 16;"
                         :: "r"(dst + 16u * (unsigned)t), "l"(src + t));
        }
        asm volatile("cp.async.commit_group;");
    }

    const int g    = warp >> 1;
    const int half = warp & 1;
    bool first = true;

    for (int nb0 = 0; nb0 < npc; nb0 += NB) {
        const int nodeBase = blockIdx.x * npc + nb0;
        if (nodeBase >= n) break;
        if (!first) __syncthreads();        // smem reuse fence vs prev epilogue

        // ---- children -> max -> exp -> smem (8 warps cover NB=16 nodes) ----
        for (int nb = warp; nb < NB; nb += 8) {
            int node = nodeBase + nb;
            if (node < n) {
                const float* L = child + (size_t)(2 * node) * OC;
                const float* R = L + OC;
                float l0 = L[lane], l1 = L[lane + 32];
                float r0 = R[lane], r1 = R[lane + 32];
                float mL = fmaxf(l0, l1), mR = fmaxf(r0, r1);
                #pragma unroll
                for (int s = 16; s > 0; s >>= 1) {
                    mL = fmaxf(mL, __shfl_xor_sync(0xffffffffu, mL, s));
                    mR = fmaxf(mR, __shfl_xor_sync(0xffffffffu, mR, s));
                }
                eLs[lane * NB + nb]        = __expf(l0 - mL);
                eLs[(lane + 32) * NB + nb] = __expf(l1 - mL);
                eRs[nb * 64 + lane]        = __expf(r0 - mR);
                eRs[nb * 64 + lane + 32]   = __expf(r1 - mR);
                if (lane == 0) base_s[nb] = mL + mR;
            } else {
                eLs[lane * NB + nb] = 0.0f;  eLs[(lane + 32) * NB + nb] = 0.0f;
                eRs[nb * 64 + lane] = 0.0f;  eRs[nb * 64 + lane + 32]   = 0.0f;
                if (lane == 0) base_s[nb] = 0.0f;
            }
        }
        if (first) { asm volatile("cp.async.wait_group 0;"); first = false; }
        __syncthreads();

        // ---- mainloop: 32 i's from smem ET, FFMA2 over 16 accumulators ----
        // A0[p]: (nb=2p, j0) , (nb=2p+1, j0);  A1[p]: same nbs for j1.
        unsigned long long A0[8], A1[8];
        #pragma unroll
        for (int p = 0; p < 8; p++) { A0[p] = 0ull; A1[p] = 0ull; }

        const float2* ets = reinterpret_cast<const float2*>(ET_s + g * 4096);
        const int ib = half * 32;
        #pragma unroll 4
        for (int ii = 0; ii < 32; ii++) {
            const int i = ib + ii;
            float2 e = ets[i * 32 + lane];               // ET[o, i, 2lane..+1]
            unsigned long long exx = pack2(e.x, e.x);
            unsigned long long eyy = pack2(e.y, e.y);
            const unsigned long long* el =
                reinterpret_cast<const unsigned long long*>(eLs + i * NB);
            #pragma unroll
            for (int p = 0; p < 8; p++) {
                unsigned long long w = el[p];            // broadcast LDS.64
                ffma2(A0[p], exx, w);
                ffma2(A1[p], eyy, w);
            }
        }

        // ---- fold eR, warp-reduce, stash partials ----
        #pragma unroll
        for (int p = 0; p < 8; p++) {
            float a0x, a0y, a1x, a1y;
            unpack2(A0[p], a0x, a0y);
            unpack2(A1[p], a1x, a1y);
            #pragma unroll
            for (int h = 0; h < 2; h++) {
                const int nb = 2 * p + h;
                const float aj0 = h ? a0y : a0x;
                const float aj1 = h ? a1y : a1x;
                float2 er = reinterpret_cast<const float2*>(eRs + nb * 64)[lane];
                float v = aj0 * er.x + aj1 * er.y;
                #pragma unroll
                for (int s = 16; s > 0; s >>= 1)
                    v += __shfl_xor_sync(0xffffffffu, v, s);
                if (lane == 0) part[(g * NB + nb) * 2 + half] = v;
            }
        }
        __syncthreads();

        // ---- epilogue: combine halves, log, write ----
        if (tid < 64) {
            const int gg = tid >> 4, nb = tid & 15;
            const int node = nodeBase + nb;
            if (node < n) {
                float v = part[(gg * NB + nb) * 2] + part[(gg * NB + nb) * 2 + 1];
                const int oo = og * 4 + gg;
                out[(size_t)node * OC + oo] =
                    parent[(size_t)node * OC + oo] + base_s[nb] + logf(v);
            }
        }
    }
}

// ---------------------------------------------------------------------------
// Host side
// ---------------------------------------------------------------------------
#define LEVEL_SMEM ((16384 + 64 * NB + NB * 64 + NB + 4 * NB * 2) * 4)

extern "C" void kernel_launch(void* const* d_in, const int* in_sizes, int n_in,
                              void* d_out, int out_size)
{
    const float* node_state = (const float*)d_in[0];
    const float* trans      = (const float*)d_in[1];
    if (n_in >= 2 && in_sizes[0] == 262144) {   // defensive input identification
        const float* t = node_state; node_state = trans; trans = t;
    }

    cudaFuncSetAttribute(level_kernel,
                         cudaFuncAttributeMaxDynamicSharedMemorySize, LEVEL_SMEM);

    expT_kernel<<<1024, 256>>>(trans);

    const float* leaves = node_state + (size_t)1023 * OC;
    float* outp = (float*)d_out;

    // n, gx, child_sel (0=leaves,1=A,2=B), out_sel (1=A,2=B,3=d_out)
    const int sched[10][4] = {
        {512, 16, 0, 1},
        {256, 16, 1, 2},
        {128,  8, 2, 1},
        { 64,  4, 1, 2},
        { 32,  2, 2, 1},
        { 16,  1, 1, 2},
        {  8,  1, 2, 1},
        {  4,  1, 1, 2},
        {  2,  1, 2, 1},
        {  1,  1, 1, 3},
    };
    for (int l = 0; l < 10; l++) {
        const int n  = sched[l][0];
        const int gx = sched[l][1];
        const int npc = (n + gx - 1) / gx;
        dim3 grid(gx, 16);
        const float* parent = node_state + (size_t)(n - 1) * OC;
        level_kernel<<<grid, 256, LEVEL_SMEM>>>(
            leaves, parent, outp, n, npc, sched[l][2], sched[l][3]);
    }
}

// round 5
// speedup vs baseline: 1.1108x; 1.1108x over previous
#include <cuda_runtime.h>
#include <cstdint>
#include <math.h>

// BinaryTreeLatentVariable: N_LEAVES=1024, L=16, C=4.
// out[node,o] = parent[node,o] + mL + mR
//             + log( sum_{i,j} expT[o,i,j] * exp(L[i]-mL) * exp(R[j]-mR) )
// Persistent kernel: 256 CTAs, software grid barrier between the 10 levels,
// ET (exp(trans)) slice resident in smem for the whole tree.

#define OC 64
#define KD 4096
#define OG 32          // o-groups; each CTA owns 2 outputs
#define XS 8           // node slices
#define NCTA (OG * XS) // 256

__device__ float g_ET[OC * KD];      // 1 MB: exp(trans) repacked [o][i][j]
__device__ float g_bufA[512 * OC];
__device__ float g_bufB[512 * OC];
__device__ unsigned int g_bar;

// ---- packed f32x2 helpers (Blackwell FFMA2) --------------------------------
__device__ __forceinline__ unsigned long long pack2(float x, float y) {
    unsigned long long r;
    asm("mov.b64 %0, {%1, %2};" : "=l"(r) : "f"(x), "f"(y));
    return r;
}
__device__ __forceinline__ void unpack2(unsigned long long v, float& x, float& y) {
    asm("mov.b64 {%0, %1}, %2;" : "=f"(x), "=f"(y) : "l"(v));
}
__device__ __forceinline__ void ffma2(unsigned long long& d,
                                      unsigned long long a, unsigned long long b) {
    asm("fma.rn.f32x2 %0, %1, %2, %0;" : "+l"(d) : "l"(a), "l"(b));
}

// ---- Prologue: ET[o][i][j] = exp(trans[...]); also reset the grid barrier --
__global__ void expT_kernel(const float* __restrict__ trans) {
    if (blockIdx.x == 0 && threadIdx.x == 0) g_bar = 0u;
    int idx = blockIdx.x * 256 + threadIdx.x;   // 0 .. 262143
    int o = idx >> 12, i = (idx >> 6) & 63, j = idx & 63;
    int lp = o >> 2, cp = o & 3;
    int ll = i >> 2, cl = i & 3;
    int lr = j >> 2, cr = j & 3;
    int src = ((((lp * 16 + ll) * 16 + lr) * 4 + cp) * 4 + cl) * 4 + cr;
    g_ET[idx] = expf(trans[src]);
}

// ---------------------------------------------------------------------------
// One chunk of NBX nodes. 8 warps: warp w -> output g=w>>2 (of the CTA's 2),
// i-quarter q=w&3 (16 i's). Lane owns j = {2*lane, 2*lane+1}.
// ---------------------------------------------------------------------------
template <int NBX>
__device__ __forceinline__ void do_chunk(
    int nodeBase, int nend,
    const float* __restrict__ child, const float* __restrict__ parent,
    float* __restrict__ out,
    const float* ET_s, float* eLs, float* eRs, float* base_s, float* part,
    int og, int warp, int lane, int g, int q)
{
    constexpr int NP = NBX / 2;
    const int tid = warp * 32 + lane;

    __syncthreads();   // smem reuse fence vs previous chunk's epilogue

    // ---- children -> per-node max -> exp -> smem ----
    for (int nb = warp; nb < NBX; nb += 8) {
        int node = nodeBase + nb;
        if (node < nend) {
            const float* L = child + (size_t)(2 * node) * OC;
            const float* R = L + OC;
            float l0 = L[lane], l1 = L[lane + 32];
            float r0 = R[lane], r1 = R[lane + 32];
            float mL = fmaxf(l0, l1), mR = fmaxf(r0, r1);
            #pragma unroll
            for (int s = 16; s > 0; s >>= 1) {
                mL = fmaxf(mL, __shfl_xor_sync(0xffffffffu, mL, s));
                mR = fmaxf(mR, __shfl_xor_sync(0xffffffffu, mR, s));
            }
            eLs[lane * NBX + nb]        = __expf(l0 - mL);
            eLs[(lane + 32) * NBX + nb] = __expf(l1 - mL);
            eRs[nb * 64 + lane]         = __expf(r0 - mR);
            eRs[nb * 64 + lane + 32]    = __expf(r1 - mR);
            if (lane == 0) base_s[nb] = mL + mR;
        } else {
            eLs[lane * NBX + nb] = 0.0f;  eLs[(lane + 32) * NBX + nb] = 0.0f;
            eRs[nb * 64 + lane]  = 0.0f;  eRs[nb * 64 + lane + 32]    = 0.0f;
            if (lane == 0) base_s[nb] = 0.0f;
        }
    }
    __syncthreads();

    // ---- mainloop: 16 i's from smem ET, FFMA2, eL via LDS.128 broadcast ----
    unsigned long long A0[NP], A1[NP];
    #pragma unroll
    for (int p = 0; p < NP; p++) { A0[p] = 0ull; A1[p] = 0ull; }

    const float2* ets = reinterpret_cast<const float2*>(ET_s + g * KD);
    const int ib = q * 16;
    #pragma unroll
    for (int ii = 0; ii < 16; ii++) {
        const int i = ib + ii;
        float2 e = ets[i * 32 + lane];                   // ET[o, i, 2lane..+1]
        unsigned long long exx = pack2(e.x, e.x);
        unsigned long long eyy = pack2(e.y, e.y);
        const float4* el4 = reinterpret_cast<const float4*>(eLs + i * NBX);
        #pragma unroll
        for (int pp = 0; pp < NBX / 4; pp++) {
            float4 v = el4[pp];                          // 4 nodes, one LDS.128
            unsigned long long w0 = pack2(v.x, v.y);
            unsigned long long w1 = pack2(v.z, v.w);
            ffma2(A0[2 * pp],     exx, w0);
            ffma2(A1[2 * pp],     eyy, w0);
            ffma2(A0[2 * pp + 1], exx, w1);
            ffma2(A1[2 * pp + 1], eyy, w1);
        }
    }

    // ---- fold eR, warp-reduce, stash quarter-partials ----
    #pragma unroll
    for (int p = 0; p < NP; p++) {
        float a0x, a0y, a1x, a1y;
        unpack2(A0[p], a0x, a0y);
        unpack2(A1[p], a1x, a1y);
        #pragma unroll
        for (int h = 0; h < 2; h++) {
            const int nb = 2 * p + h;
            const float aj0 = h ? a0y : a0x;
            const float aj1 = h ? a1y : a1x;
            float2 er = reinterpret_cast<const float2*>(eRs + nb * 64)[lane];
            float v = aj0 * er.x + aj1 * er.y;
            #pragma unroll
            for (int s = 16; s > 0; s >>= 1)
                v += __shfl_xor_sync(0xffffffffu, v, s);
            if (lane == 0) part[(g * 16 + nb) * 4 + q] = v;
        }
    }
    __syncthreads();

    // ---- epilogue: combine quarters, log, write ----
    if (tid < 2 * NBX) {
        const int gg = tid / NBX, nb = tid % NBX;
        const int node = nodeBase + nb;
        if (node < nend) {
            const float* pr = part + (gg * 16 + nb) * 4;
            float v = (pr[0] + pr[1]) + (pr[2] + pr[3]);
            const int o = og * 2 + gg;
            out[(size_t)node * OC + o] =
                parent[(size_t)node * OC + o] + base_s[nb] + logf(v);
        }
    }
}

// ---------------------------------------------------------------------------
// Persistent tree kernel: all 10 levels, grid barrier between them.
// ---------------------------------------------------------------------------
__global__ __launch_bounds__(256, 2) void tree_kernel(
    const float* __restrict__ node_state, float* __restrict__ d_out)
{
    extern __shared__ float smem[];
    float* ET_s   = smem;                  // 2*4096 = 8192 floats (32 KB)
    float* eLs    = smem + 8192;           // [i][nb]  64*16
    float* eRs    = eLs + 64 * 16;         // [nb][j]  16*64
    float* base_s = eRs + 16 * 64;         // 16
    float* part   = base_s + 16;           // [g][nb][q]  2*16*4

    const int tid  = threadIdx.x;
    const int warp = tid >> 5;
    const int lane = tid & 31;
    const int og   = blockIdx.x & (OG - 1);
    const int xs   = blockIdx.x >> 5;      // 0..7
    const int g    = warp >> 2;            // output within CTA's pair
    const int q    = warp & 3;             // i-quarter

    // ---- one-time ET slice fill: 32 KB via cp.async ----
    {
        unsigned int dst;
        asm("{ .reg .u64 t; cvta.to.shared.u64 t, %1; cvt.u32.u64 %0, t; }"
            : "=r"(dst) : "l"(ET_s));
        const float4* src = reinterpret_cast<const float4*>(g_ET)
                            + (size_t)og * 2048;
        #pragma unroll
        for (int t = 0; t < 8; t++) {
            int e = tid + t * 256;
            asm volatile("cp.async.cg.shared.global [%0], [%1], 16;"
                         :: "r"(dst + 16u * (unsigned)e), "l"(src + e));
        }
        asm volatile("cp.async.commit_group;");
        asm volatile("cp.async.wait_group 0;");
    }
    __syncthreads();

    const float* leaves = node_state + (size_t)1023 * OC;

    #pragma unroll 1
    for (int l = 0; l < 10; l++) {
        const int n = 512 >> l;
        const float* child = (l == 0) ? leaves : ((l & 1) ? g_bufA : g_bufB);
        float* out = (l == 9) ? d_out : ((l & 1) ? g_bufB : g_bufA);
        const float* parent = node_state + (size_t)(n - 1) * OC;

        const int npc    = (n + XS - 1) / XS;
        const int nstart = xs * npc;
        const int nend   = (nstart + npc < n) ? (nstart + npc) : n;

        if (nstart < n) {
            if (npc >= 16) {
                for (int nb0 = nstart; nb0 < nend; nb0 += 16)
                    do_chunk<16>(nb0, nend, child, parent, out,
                                 ET_s, eLs, eRs, base_s, part,
                                 og, warp, lane, g, q);
            } else {
                for (int nb0 = nstart; nb0 < nend; nb0 += 4)
                    do_chunk<4>(nb0, nend, child, parent, out,
                                ET_s, eLs, eRs, base_s, part,
                                og, warp, lane, g, q);
            }
        }

        // ---- grid barrier (except after last level) ----
        if (l < 9) {
            __syncthreads();
            if (tid == 0) {
                __threadfence();
                atomicAdd(&g_bar, 1u);
                const unsigned int tgt = (unsigned int)(l + 1) * NCTA;
                while (*(volatile unsigned int*)&g_bar < tgt) { }
                __threadfence();
            }
            __syncthreads();
        }
    }
}

// ---------------------------------------------------------------------------
// Host side
// ---------------------------------------------------------------------------
#define TREE_SMEM ((8192 + 64 * 16 + 16 * 64 + 16 + 2 * 16 * 4) * 4)

extern "C" void kernel_launch(void* const* d_in, const int* in_sizes, int n_in,
                              void* d_out, int out_size)
{
    const float* node_state = (const float*)d_in[0];
    const float* trans      = (const float*)d_in[1];
    if (n_in >= 2 && in_sizes[0] == 262144) {   // defensive input identification
        const float* t = node_state; node_state = trans; trans = t;
    }

    cudaFuncSetAttribute(tree_kernel,
                         cudaFuncAttributeMaxDynamicSharedMemorySize, TREE_SMEM);

    expT_kernel<<<1024, 256>>>(trans);
    tree_kernel<<<NCTA, 256, TREE_SMEM>>>(node_state, (float*)d_out);
}